// round 13
// baseline (speedup 1.0000x reference)
#include <cuda_runtime.h>
#include <math.h>

#define B_   256
#define T_   64
#define H_   256
#define D_   512
#define NCTA 128
#define NTHR 256
#define CLSZ 8

#define PAD  260
#define SA0_OFF  0                      // A buffer phase 0: 8 chunks x 512 fl
#define SA1_OFF  4096                   // A buffer phase 1
#define SWC_OFF  8192                   // Wc tile [32][PAD]
#define SWH_OFF  (SWC_OFF + 32 * PAD)   // W_hh gate tiles [3][32][PAD] (+scratch)
#define SMEM_FLOATS (SWH_OFF + 3 * 32 * PAD)

#define W2T_STRIDE 36
#define CHUNK_BYTES 2048

__device__ __forceinline__ unsigned s2u(const void* p) {
    unsigned a;
    asm("{ .reg .u64 t; cvta.to.shared.u64 t, %1; cvt.u32.u64 %0, t; }"
        : "=r"(a) : "l"(p));
    return a;
}

__device__ __forceinline__ void mwait(unsigned mbar, unsigned parity) {
    asm volatile(
        "{\n\t"
        ".reg .pred P;\n\t"
        "MW_LOOP_%=:\n\t"
        "mbarrier.try_wait.parity.shared.b64 P, [%0], %1;\n\t"
        "@!P bra MW_LOOP_%=;\n\t"
        "}"
        :: "r"(mbar), "r"(parity) : "memory");
}

__device__ __forceinline__ void arm_tx(unsigned mbar, unsigned bytes) {
    asm volatile("mbarrier.arrive.expect_tx.shared.b64 _, [%0], %1;"
                 :: "r"(mbar), "r"(bytes) : "memory");
}

__device__ __forceinline__ void bulk_dsmem(unsigned dst, unsigned src,
                                           unsigned bytes, unsigned dmbar) {
    asm volatile(
        "cp.async.bulk.shared::cluster.shared::cta.mbarrier::complete_tx::bytes "
        "[%0], [%1], %2, [%3];"
        :: "r"(dst), "r"(src), "r"(bytes), "r"(dmbar) : "memory");
}

// packed f32x2 fma: d.lo += a.lo*b.lo ; d.hi += a.hi*b.hi
__device__ __forceinline__ void fma2(unsigned long long &d,
                                     unsigned long long a,
                                     unsigned long long b) {
    asm("fma.rn.f32x2 %0, %1, %2, %0;" : "+l"(d) : "l"(a), "l"(b));
}
__device__ __forceinline__ float redu2(unsigned long long v) {
    float a, b;
    asm("mov.b64 {%0, %1}, %2;" : "=f"(a), "=f"(b) : "l"(v));
    return a + b;
}

__device__ __forceinline__ float sigm(float x) { return 1.f / (1.f + expf(-x)); }

// ---------------- persistent-group kernel ------------------------------------
__global__ void __launch_bounds__(NTHR, 1) __cluster_dims__(CLSZ, 1, 1)
ode_rnn_kernel(const float* __restrict__ batch, const float* __restrict__ mask,
               const float* __restrict__ W1,   const float* __restrict__ b1,
               const float* __restrict__ W2,   const float* __restrict__ b2,
               const float* __restrict__ W_ih, const float* __restrict__ b_ih,
               const float* __restrict__ W_hh, const float* __restrict__ b_hh,
               float* __restrict__ out)
{
    extern __shared__ float sm[];
    float* sWc  = sm + SWC_OFF;
    float* sWh  = sm + SWH_OFF;
    float* sW2T = sm + SWH_OFF;   // setup scratch overlays sWh

    __shared__ __align__(16) unsigned long long s_mbar[16];   // [phase][chunk]

    const int tid = threadIdx.x;
    const int mt  = blockIdx.x >> 3;
    const int nt  = blockIdx.x & 7;
    const int m0  = mt << 4;
    const int n0  = nt << 5;
    const int w   = tid >> 5;
    const int l   = tid & 31;
    const int jc  = (w << 2) + (l & 3);
    const int r1  = l >> 2;
    const int r2  = r1 + 8;

    const int b1r = m0 + r1;
    const int b2r = m0 + r2;
    const int j   = n0 + jc;

    const unsigned smbase = s2u(sm);
    const unsigned mbase  = s2u(s_mbar);

    // ================= setup =================
    for (int idx = tid; idx < 4096; idx += NTHR) sm[SA0_OFF + idx] = 0.f;

    for (int idx = tid; idx < 32 * (D_ / 4); idx += NTHR) {
        int jj = idx >> 7;
        int d4 = (idx & 127) << 2;
        float4 v = __ldg((const float4*)&W2[(size_t)(n0 + jj) * D_ + d4]);
        sW2T[(d4 + 0) * W2T_STRIDE + jj] = v.x;
        sW2T[(d4 + 1) * W2T_STRIDE + jj] = v.y;
        sW2T[(d4 + 2) * W2T_STRIDE + jj] = v.z;
        sW2T[(d4 + 3) * W2T_STRIDE + jj] = v.w;
    }
    __syncthreads();

    #pragma unroll 1
    for (int p = 0; p < 2; p++) {
        float acc[16];
        #pragma unroll
        for (int jj = 0; jj < 16; jj++) acc[jj] = 0.f;
        for (int d = 0; d < D_; d++) {
            float w1v = __ldg(&W1[(size_t)d * H_ + tid]);
            const float* w2d = &sW2T[d * W2T_STRIDE + p * 16];
            #pragma unroll
            for (int jj = 0; jj < 16; jj += 4) {
                float4 wv = *(const float4*)(w2d + jj);
                acc[jj + 0] += wv.x * w1v;
                acc[jj + 1] += wv.y * w1v;
                acc[jj + 2] += wv.z * w1v;
                acc[jj + 3] += wv.w * w1v;
            }
        }
        #pragma unroll
        for (int jj = 0; jj < 16; jj++)
            sWc[(p * 16 + jj) * PAD + tid] = acc[jj];
    }
    float c_bc;
    {
        float s = 0.f;
        for (int d = 0; d < D_; d++)
            s += sW2T[d * W2T_STRIDE + jc] * __ldg(&b1[d]);
        c_bc = s + __ldg(&b2[j]);
    }
    __syncthreads();

    for (int idx = tid; idx < 3 * 32 * 64; idx += NTHR) {
        int g = idx >> 11, r = (idx >> 6) & 31, q = (idx & 63) << 2;
        float4 v = __ldg((const float4*)&W_hh[(size_t)(g * H_ + n0 + r) * H_ + q]);
        *(float4*)&sWh[(g * 32 + r) * PAD + q] = v;
    }

    const float c_bhr = __ldg(&b_hh[j]);
    const float c_bhz = __ldg(&b_hh[j + 256]);
    const float c_bhn = __ldg(&b_hh[j + 512]);
    const float c_wir = __ldg(&W_ih[j]);
    const float c_wiz = __ldg(&W_ih[j + 256]);
    const float c_win = __ldg(&W_ih[j + 512]);
    const float c_bir = __ldg(&b_ih[j]);
    const float c_biz = __ldg(&b_ih[j + 256]);
    const float c_bin = __ldg(&b_ih[j + 512]);

    if (tid < 16) {
        asm volatile("mbarrier.init.shared.b64 [%0], 1;"
                     :: "r"(mbase + tid * 8) : "memory");
    }
    __syncthreads();
    asm volatile("barrier.cluster.arrive.aligned;" ::: "memory");
    asm volatile("barrier.cluster.wait.aligned;"   ::: "memory");

    unsigned rbase[CLSZ], rmbar[CLSZ];
    #pragma unroll
    for (int p = 0; p < CLSZ; p++) {
        asm("mapa.shared::cluster.u32 %0, %1, %2;" : "=r"(rbase[p]) : "r"(smbase), "r"(p));
        asm("mapa.shared::cluster.u32 %0, %1, %2;" : "=r"(rmbar[p]) : "r"(mbase),  "r"(p));
    }

    const int soff1 = r1 * 32 + (((w ^ r1) << 2) | (l & 3));
    const int soff2 = soff1 + 256;

    const float* pbc = sWc + jc * PAD;
    const float* pbr = sWh + (0 * 32 + jc) * PAD;
    const float* pbz = sWh + (1 * 32 + jc) * PAD;
    const float* pbn = sWh + (2 * 32 + jc) * PAD;

    float ry1 = 0.f, ry2 = 0.f;
    float k11 = 0.f, k12 = 0.f;

    // ================= time loop =================
    int   s = 0;
    float tprev = 0.f;
    #pragma unroll 1
    for (int t = 0; t < T_; t++) {
        const float tcur  = __ldg(&batch[2 * t]);
        const float hstep = tcur - tprev;
        tprev = tcur;

        #pragma unroll 1
        for (int i = 0; i < 4; i++) {
            const bool gru  = (i == 3);
            const bool last = gru && (t == T_ - 1);
            if (!last && tid < 8 && tid != nt)
                arm_tx(mbase + (unsigned)(((s & 1) << 3) + tid) * 8u, CHUNK_BYTES);

            const float* Ab = sm + ((s & 1) ? SA1_OFF : SA0_OFF);
            const unsigned wset = (unsigned)(((s - 1) & 1) << 3);
            const unsigned wpar = (unsigned)(((s - 1) >> 1) & 1);

            float x1, x2, mk1, mk2;
            if (gru) {
                x1  = __ldg(&batch[(b1r * T_ + t) * 2 + 1]);
                x2  = __ldg(&batch[(b2r * T_ + t) * 2 + 1]);
                mk1 = __ldg(&mask[b1r * T_ + t]);
                mk2 = __ldg(&mask[b2r * T_ + t]);
            }

            // packed accumulators
            unsigned long long aA1 = 0ull, aB1 = 0ull, aA2 = 0ull, aB2 = 0ull; // ODE
            unsigned long long rA1 = 0ull, rB1 = 0ull, zA1 = 0ull, zB1 = 0ull; // GRU row1
            unsigned long long nA1 = 0ull, nB1 = 0ull;
            unsigned long long rA2 = 0ull, rB2 = 0ull, zA2 = 0ull, zB2 = 0ull; // GRU row2
            unsigned long long nA2 = 0ull, nB2 = 0ull;

            #pragma unroll 1
            for (int q = 0; q < 8; q++) {
                const int p = (nt + q) & 7;
                if (s > 0 && q > 0)
                    mwait(mbase + (wset + (unsigned)p) * 8u, wpar);
                const float* cb1 = Ab + p * 512 + r1 * 32;
                const float* cb2 = cb1 + 256;
                if (!gru) {
                    const float* bb = pbc + p * 32;
                    #pragma unroll
                    for (int c = 0; c < 8; c++) {
                        const int sc = (c ^ r1) << 2;
                        ulonglong2 bv = *(const ulonglong2*)(bb + (c << 2));
                        ulonglong2 u1 = *(const ulonglong2*)(cb1 + sc);
                        ulonglong2 u2 = *(const ulonglong2*)(cb2 + sc);
                        fma2(aA1, u1.x, bv.x);
                        fma2(aB1, u1.y, bv.y);
                        fma2(aA2, u2.x, bv.x);
                        fma2(aB2, u2.y, bv.y);
                    }
                } else {
                    const int kb = p * 32;
                    #pragma unroll
                    for (int c = 0; c < 8; c++) {
                        const int sc = (c ^ r1) << 2;
                        const int k  = kb + (c << 2);
                        ulonglong2 u1 = *(const ulonglong2*)(cb1 + sc);
                        ulonglong2 u2 = *(const ulonglong2*)(cb2 + sc);
                        ulonglong2 br = *(const ulonglong2*)(pbr + k);
                        ulonglong2 bz = *(const ulonglong2*)(pbz + k);
                        ulonglong2 bn = *(const ulonglong2*)(pbn + k);
                        fma2(rA1, u1.x, br.x); fma2(rB1, u1.y, br.y);
                        fma2(zA1, u1.x, bz.x); fma2(zB1, u1.y, bz.y);
                        fma2(nA1, u1.x, bn.x); fma2(nB1, u1.y, bn.y);
                        fma2(rA2, u2.x, br.x); fma2(rB2, u2.y, br.y);
                        fma2(zA2, u2.x, bz.x); fma2(zB2, u2.y, bz.y);
                        fma2(nA2, u2.x, bn.x); fma2(nB2, u2.y, bn.y);
                    }
                }
            }

            // ---- epilogue ----
            float u1, u2;
            if (!gru) {
                float kv1 = tanhf(redu2(aA1) + redu2(aB1) + c_bc);
                float kv2 = tanhf(redu2(aA2) + redu2(aB2) + c_bc);
                if (i == 0) {
                    k11 = kv1;  k12 = kv2;
                    u1 = ry1 + 0.5f * hstep * kv1;
                    u2 = ry2 + 0.5f * hstep * kv2;
                } else if (i == 1) {
                    u1 = ry1 + hstep * (2.f * kv1 - k11);
                    u2 = ry2 + hstep * (2.f * kv2 - k12);
                    k11 += 4.f * kv1;
                    k12 += 4.f * kv2;
                } else {
                    u1 = ry1 + (hstep * (1.f / 6.f)) * (k11 + kv1);
                    u2 = ry2 + (hstep * (1.f / 6.f)) * (k12 + kv2);
                    ry1 = u1; ry2 = u2;
                }
            } else {
                float ar1 = redu2(rA1) + redu2(rB1);
                float az1 = redu2(zA1) + redu2(zB1);
                float an1 = redu2(nA1) + redu2(nB1);
                float ar2 = redu2(rA2) + redu2(rB2);
                float az2 = redu2(zA2) + redu2(zB2);
                float an2 = redu2(nA2) + redu2(nB2);
                {
                    float r_ = sigm(x1 * c_wir + c_bir + ar1 + c_bhr);
                    float z_ = sigm(x1 * c_wiz + c_biz + az1 + c_bhz);
                    float n_ = tanhf(x1 * c_win + c_bin + r_ * (an1 + c_bhn));
                    float ht = (1.f - z_) * n_ + z_ * ry1;
                    ry1 = mk1 * ht + (1.f - mk1) * ry1;
                }
                {
                    float r_ = sigm(x2 * c_wir + c_bir + ar2 + c_bhr);
                    float z_ = sigm(x2 * c_wiz + c_biz + az2 + c_bhz);
                    float n_ = tanhf(x2 * c_win + c_bin + r_ * (an2 + c_bhn));
                    float ht = (1.f - z_) * n_ + z_ * ry2;
                    ry2 = mk2 * ht + (1.f - mk2) * ry2;
                }
                u1 = ry1; u2 = ry2;
            }

            if (!last) {
                const int nextpb = (s & 1) ? SA0_OFF : SA1_OFF;
                float* Anext = sm + nextpb + nt * 512;
                Anext[soff1] = u1;
                Anext[soff2] = u2;
                __syncthreads();
                if (tid < 8 && tid != nt) {
                    asm volatile("fence.proxy.async.shared::cta;" ::: "memory");
                    const unsigned off = (unsigned)(nextpb + nt * 512) * 4u;
                    bulk_dsmem(rbase[tid] + off, smbase + off, CHUNK_BYTES,
                               rmbar[tid] + (unsigned)(((s & 1) << 3) + nt) * 8u);
                }
            } else {
                out[b1r * H_ + j] = ry1;
                out[b2r * H_ + j] = ry2;
            }
            s++;
        }
    }
}

extern "C" void kernel_launch(void* const* d_in, const int* in_sizes, int n_in,
                              void* d_out, int out_size) {
    const float* batch = (const float*)d_in[0];
    const float* mask  = (const float*)d_in[1];
    const float* W1    = (const float*)d_in[2];
    const float* b1    = (const float*)d_in[3];
    const float* W2    = (const float*)d_in[4];
    const float* b2    = (const float*)d_in[5];
    const float* W_ih  = (const float*)d_in[6];
    const float* b_ih  = (const float*)d_in[7];
    const float* W_hh  = (const float*)d_in[8];
    const float* b_hh  = (const float*)d_in[9];
    float* out = (float*)d_out;

    cudaFuncSetAttribute(ode_rnn_kernel,
                         cudaFuncAttributeMaxDynamicSharedMemorySize,
                         SMEM_FLOATS * sizeof(float));

    ode_rnn_kernel<<<NCTA, NTHR, SMEM_FLOATS * sizeof(float)>>>(
        batch, mask, W1, b1, W2, b2, W_ih, b_ih, W_hh, b_hh, out);
}

// round 14
// speedup vs baseline: 1.3262x; 1.3262x over previous
#include <cuda_runtime.h>
#include <math.h>

#define B_   256
#define T_   64
#define H_   256
#define D_   512
#define NCTA 64
#define NTHR 512
#define ROWS 4

// ---------------- device scratch (no allocations allowed) -------------------
__device__ __align__(16) float4 g_WcB [64 * 256];   // ODE weight, blocked [kq][n]
__device__ __align__(16) float4 g_WhhB[64 * 768];   // GRU weight,  blocked [kq][gn]
__device__ float g_bc[H_];
__device__ unsigned g_arrive  = 0;
__device__ unsigned g_release = 0;

// ---------------- grid barrier (setup only; plain launch, all resident) -----
__device__ __forceinline__ void gbar(unsigned &next) {
    __threadfence();
    __syncthreads();
    if (threadIdx.x == 0) {
        unsigned tgt = next;
        if (atomicAdd(&g_arrive, 1u) == NCTA - 1) {
            g_arrive = 0;
            __threadfence();
            *(volatile unsigned*)&g_release = tgt;
        } else {
            while ((int)(*(volatile unsigned*)&g_release - tgt) < 0) { }
        }
        __threadfence();
    }
    __syncthreads();
    next++;
}

// packed f32x2 fma: d += a * b (elementwise on the two lanes)
__device__ __forceinline__ void fma2(unsigned long long &d,
                                     unsigned long long a,
                                     unsigned long long b) {
    asm("fma.rn.f32x2 %0, %1, %2, %0;" : "+l"(d) : "l"(a), "l"(b));
}
__device__ __forceinline__ float redu2(unsigned long long v) {
    float a, b;
    asm("mov.b64 {%0, %1}, %2;" : "=f"(a), "=f"(b) : "l"(v));
    return a + b;
}
__device__ __forceinline__ float sigm(float x) { return 1.f / (1.f + expf(-x)); }

// ---------------- kernel ------------------------------------------------------
__global__ void __launch_bounds__(NTHR, 1)
ode_rnn_kernel(const float* __restrict__ batch, const float* __restrict__ mask,
               const float* __restrict__ W1,   const float* __restrict__ b1,
               const float* __restrict__ W2,   const float* __restrict__ b2,
               const float* __restrict__ W_ih, const float* __restrict__ b_ih,
               const float* __restrict__ W_hh, const float* __restrict__ b_hh,
               float* __restrict__ out)
{
    __shared__ __align__(16) float su[ROWS * H_];                 // state u (4 rows)
    __shared__ __align__(16) unsigned long long red[12 * 256];    // reduce buffer
    __shared__ __align__(16) float sW2T[D_ * ROWS];               // setup scratch

    const int tid = threadIdx.x;
    const int n   = tid & 255;        // owned feature column (t<256 also epilogue owner)
    const int hh  = tid >> 8;         // k-half: 0 -> k[0,128), 1 -> k[128,256)
    const int n0  = blockIdx.x * ROWS;    // this CTA's Wc setup column block
    const int m0  = blockIdx.x * ROWS;    // this CTA's batch rows

    __shared__ unsigned s_base;
    if (tid == 0) s_base = *(volatile unsigned*)&g_release;
    __syncthreads();
    unsigned bar = s_base + 1;

    // ================= setup =================
    // stage W2 rows n0..n0+3 transposed: sW2T[d*4 + p]
    for (int idx = tid; idx < ROWS * D_; idx += NTHR) {
        int p = idx >> 9;              // 0..3
        int d = idx & 511;
        sW2T[d * 4 + p] = __ldg(&W2[(size_t)(n0 + p) * D_ + d]);
    }
    __syncthreads();

    // WcB block: Wc[n0+p][4kq..4kq+3] = sum_d W2[n0+p][d] * W1[d][4kq..4kq+3]
    if (tid < 256) {
        const int kq = tid & 63;
        const int p  = tid >> 6;
        float4 acc = make_float4(0.f, 0.f, 0.f, 0.f);
        for (int d = 0; d < D_; d++) {
            float4 w1 = __ldg((const float4*)&W1[(size_t)d * H_ + 4 * kq]);
            float  s  = sW2T[d * 4 + p];
            acc.x += s * w1.x;  acc.y += s * w1.y;
            acc.z += s * w1.z;  acc.w += s * w1.w;
        }
        g_WcB[kq * 256 + n0 + p] = acc;
    }
    if (tid < ROWS) {   // bc[n0+tid]
        float s = 0.f;
        for (int d = 0; d < D_; d++) s += sW2T[d * 4 + tid] * __ldg(&b1[d]);
        g_bc[n0 + tid] = s + __ldg(&b2[n0 + tid]);
    }
    // WhhB rearrange: [kq][gn] <- W_hh[gn][4kq..4kq+3]   (grid-stride)
    for (int idx = blockIdx.x * NTHR + tid; idx < 64 * 768; idx += NCTA * NTHR) {
        int gn = idx >> 6;
        int kq = idx & 63;
        g_WhhB[kq * 768 + gn] = __ldg((const float4*)&W_hh[(size_t)gn * H_ + 4 * kq]);
    }
    gbar(bar);     // blocked weights + bc globally visible

    // per-thread constants (epilogue owners only)
    float c_bc = 0.f, c_bhr = 0.f, c_bhz = 0.f, c_bhn = 0.f;
    float c_wir = 0.f, c_wiz = 0.f, c_win = 0.f;
    float c_bir = 0.f, c_biz = 0.f, c_bin = 0.f;
    if (tid < 256) {
        c_bc  = __ldg(&g_bc[n]);
        c_bhr = __ldg(&b_hh[n]);
        c_bhz = __ldg(&b_hh[n + 256]);
        c_bhn = __ldg(&b_hh[n + 512]);
        c_wir = __ldg(&W_ih[n]);
        c_wiz = __ldg(&W_ih[n + 256]);
        c_win = __ldg(&W_ih[n + 512]);
        c_bir = __ldg(&b_ih[n]);
        c_biz = __ldg(&b_ih[n + 256]);
        c_bin = __ldg(&b_ih[n + 512]);
    }

    // init state u = 0
    for (int idx = tid; idx < ROWS * H_; idx += NTHR) su[idx] = 0.f;
    __syncthreads();

    float ry[ROWS]  = {0.f, 0.f, 0.f, 0.f};   // ODE base state (rows m0..m0+3, col n)
    float k11[ROWS] = {0.f, 0.f, 0.f, 0.f};   // RK3 k1 keep

    const int kq0 = hh << 5;           // weight block row offset (0 or 32)
    const int kb  = hh << 7;           // k offset in su (0 or 128)

    // ================= time loop =================
    float tprev = 0.f;
    #pragma unroll 1
    for (int t = 0; t < T_; t++) {
        const float tcur  = __ldg(&batch[2 * t]);
        const float hstep = tcur - tprev;
        tprev = tcur;

        #pragma unroll 1
        for (int i = 0; i < 4; i++) {
            const bool gru  = (i == 3);
            const bool last = gru && (t == T_ - 1);

            if (!gru) {
                // ---- ODE GEMM: 4 rows x 1 col x 128 k (per thread) ----
                unsigned long long a0 = 0ull, a1 = 0ull, a2 = 0ull, a3 = 0ull;
                const float4* wp = g_WcB + kq0 * 256 + n;
                #pragma unroll
                for (int b = 0; b < 32; b++) {
                    ulonglong2 w2 = __ldg((const ulonglong2*)(wp + b * 256));
                    const float* up = su + kb + (b << 2);
                    ulonglong2 u0 = *(const ulonglong2*)(up);
                    ulonglong2 u1 = *(const ulonglong2*)(up + 256);
                    ulonglong2 u2 = *(const ulonglong2*)(up + 512);
                    ulonglong2 u3 = *(const ulonglong2*)(up + 768);
                    fma2(a0, u0.x, w2.x); fma2(a0, u0.y, w2.y);
                    fma2(a1, u1.x, w2.x); fma2(a1, u1.y, w2.y);
                    fma2(a2, u2.x, w2.x); fma2(a2, u2.y, w2.y);
                    fma2(a3, u3.x, w2.x); fma2(a3, u3.y, w2.y);
                }
                if (tid >= 256) {
                    red[0 * 256 + n] = a0;
                    red[1 * 256 + n] = a1;
                    red[2 * 256 + n] = a2;
                    red[3 * 256 + n] = a3;
                }
                __syncthreads();
                if (tid < 256) {
                    float dot[ROWS];
                    dot[0] = redu2(a0) + redu2(red[0 * 256 + n]);
                    dot[1] = redu2(a1) + redu2(red[1 * 256 + n]);
                    dot[2] = redu2(a2) + redu2(red[2 * 256 + n]);
                    dot[3] = redu2(a3) + redu2(red[3 * 256 + n]);
                    #pragma unroll
                    for (int r = 0; r < ROWS; r++) {
                        float kv = tanhf(dot[r] + c_bc);
                        float u;
                        if (i == 0) {
                            k11[r] = kv;
                            u = ry[r] + 0.5f * hstep * kv;
                        } else if (i == 1) {
                            u = ry[r] + hstep * (2.f * kv - k11[r]);
                            k11[r] += 4.f * kv;
                        } else {
                            u = ry[r] + (hstep * (1.f / 6.f)) * (k11[r] + kv);
                            ry[r] = u;
                        }
                        su[r * 256 + n] = u;
                    }
                }
                __syncthreads();
            } else {
                // ---- GRU GEMM: 4 rows x 3 gate-cols x 128 k (per thread) ----
                unsigned long long g0[ROWS] = {0,0,0,0};   // r gate
                unsigned long long g1[ROWS] = {0,0,0,0};   // z gate
                unsigned long long g2[ROWS] = {0,0,0,0};   // n gate
                const float4* wpr = g_WhhB + kq0 * 768 + n;
                #pragma unroll
                for (int b = 0; b < 32; b++) {
                    ulonglong2 wr = __ldg((const ulonglong2*)(wpr + b * 768));
                    ulonglong2 wz = __ldg((const ulonglong2*)(wpr + b * 768 + 256));
                    ulonglong2 wn = __ldg((const ulonglong2*)(wpr + b * 768 + 512));
                    const float* up = su + kb + (b << 2);
                    #pragma unroll
                    for (int r = 0; r < ROWS; r++) {
                        ulonglong2 u2 = *(const ulonglong2*)(up + r * 256);
                        fma2(g0[r], u2.x, wr.x); fma2(g0[r], u2.y, wr.y);
                        fma2(g1[r], u2.x, wz.x); fma2(g1[r], u2.y, wz.y);
                        fma2(g2[r], u2.x, wn.x); fma2(g2[r], u2.y, wn.y);
                    }
                }
                if (tid >= 256) {
                    #pragma unroll
                    for (int r = 0; r < ROWS; r++) {
                        red[(0 * 4 + r) * 256 + n] = g0[r];
                        red[(1 * 4 + r) * 256 + n] = g1[r];
                        red[(2 * 4 + r) * 256 + n] = g2[r];
                    }
                }
                __syncthreads();
                if (tid < 256) {
                    #pragma unroll
                    for (int r = 0; r < ROWS; r++) {
                        float ar = redu2(g0[r]) + redu2(red[(0 * 4 + r) * 256 + n]);
                        float az = redu2(g1[r]) + redu2(red[(1 * 4 + r) * 256 + n]);
                        float an = redu2(g2[r]) + redu2(red[(2 * 4 + r) * 256 + n]);
                        const int brow = m0 + r;
                        float x  = __ldg(&batch[(brow * T_ + t) * 2 + 1]);
                        float mk = __ldg(&mask[brow * T_ + t]);
                        float r_ = sigm(x * c_wir + c_bir + ar + c_bhr);
                        float z_ = sigm(x * c_wiz + c_biz + az + c_bhz);
                        float n_ = tanhf(x * c_win + c_bin + r_ * (an + c_bhn));
                        float ht = (1.f - z_) * n_ + z_ * ry[r];
                        ry[r] = mk * ht + (1.f - mk) * ry[r];
                        su[r * 256 + n] = ry[r];
                        if (last) out[brow * H_ + n] = ry[r];
                    }
                }
                __syncthreads();
            }
        }
    }
}

extern "C" void kernel_launch(void* const* d_in, const int* in_sizes, int n_in,
                              void* d_out, int out_size) {
    const float* batch = (const float*)d_in[0];
    const float* mask  = (const float*)d_in[1];
    const float* W1    = (const float*)d_in[2];
    const float* b1    = (const float*)d_in[3];
    const float* W2    = (const float*)d_in[4];
    const float* b2    = (const float*)d_in[5];
    const float* W_ih  = (const float*)d_in[6];
    const float* b_ih  = (const float*)d_in[7];
    const float* W_hh  = (const float*)d_in[8];
    const float* b_hh  = (const float*)d_in[9];
    float* out = (float*)d_out;

    ode_rnn_kernel<<<NCTA, NTHR>>>(batch, mask, W1, b1, W2, b2,
                                   W_ih, b_ih, W_hh, b_hh, out);
}